// round 5
// baseline (speedup 1.0000x reference)
#include <cuda_runtime.h>

// F[8,16384,12] f32 -> out [8,12,16384] f32
#define NV      12
#define SEQ_N   16384
#define ROWS    131072                  // 8 * 16384
#define TOTAL   (ROWS * NV)             // 1572864
#define TPB_A   128
#define ROWS_PER_BLK (TPB_A / 2)        // 64: two threads per row
#define NBLK_A  (ROWS / ROWS_PER_BLK)   // 2048
#define TPB_C   128
#define NBLK_C  1024                    // 1024*128*3 float4 = TOTAL/4
#define NEG_SLOPE 0.2f
#define BN_EPS  1e-5

typedef unsigned long long ull;

// Scratch: device globals only.
__device__ double2 g_partials[NBLK_A];

// ---------------- packed f32x2 helpers (sm_103a FFMA2 path) ----------------
__device__ __forceinline__ ull pk2(float a, float b) {
    ull r; asm("mov.b64 %0, {%1,%2};" : "=l"(r) : "f"(a), "f"(b)); return r;
}
__device__ __forceinline__ void upk2(ull v, float& a, float& b) {
    asm("mov.b64 {%0,%1}, %2;" : "=f"(a), "=f"(b) : "l"(v));
}
__device__ __forceinline__ ull add2(ull a, ull b) {
    ull r; asm("add.rn.f32x2 %0, %1, %2;" : "=l"(r) : "l"(a), "l"(b)); return r;
}
__device__ __forceinline__ ull mul2(ull a, ull b) {
    ull r; asm("mul.rn.f32x2 %0, %1, %2;" : "=l"(r) : "l"(a), "l"(b)); return r;
}
__device__ __forceinline__ ull fma2(ull a, ull b, ull c) {
    ull r; asm("fma.rn.f32x2 %0, %1, %2, %3;" : "=l"(r) : "l"(a), "l"(b), "l"(c)); return r;
}
// leaky per lane: max(x, 0.2x) = 1 packed FMUL2 + 2 scalar FMNMX (alu pipe).
__device__ __forceinline__ ull leaky2(ull v, ull k02) {
    ull t = mul2(v, k02);
    float v0, v1, t0, t1;
    upk2(v, v0, v1); upk2(t, t0, t1);
    return pk2(fmaxf(v0, t0), fmaxf(v1, t1));
}
__device__ __forceinline__ float leaky1(float x) { return fmaxf(x, NEG_SLOPE * x); }

// ---------------------------------------------------------------------------
// Kernel A: pair-MLP + conv. Two threads per row (each handles 6 of 12 i's)
// to double resident warps (8192 total) and hide the fma dependency chains.
// ---------------------------------------------------------------------------
__global__ __launch_bounds__(TPB_A)
void nlmp_main_kernel(const float* __restrict__ F,
                      const float* __restrict__ W1, const float* __restrict__ b1,
                      const float* __restrict__ W2, const float* __restrict__ b2,
                      const float* __restrict__ W3, const float* __restrict__ b3,
                      const float* __restrict__ cw, const float* __restrict__ cb,
                      float* __restrict__ y)
{
    const int tid  = threadIdx.x;
    const int half = tid >> 6;                       // 0 or 1
    const int r    = tid & 63;                       // local row
    const int t    = blockIdx.x * ROWS_PER_BLK + r;  // global row id
    const int i0   = half * (NV / 2);                // first i of my half

    // ---- scalar weights ----
    const float w100 = __ldg(W1 + 0), w101 = __ldg(W1 + 1);
    const float w110 = __ldg(W1 + 2), w111 = __ldg(W1 + 3);
    const float B10  = __ldg(b1 + 0), B11  = __ldg(b1 + 1);
    const float cw0  = __ldg(cw + 0), cw1  = __ldg(cw + 1);
    const float cb0  = __ldg(cb + 0);

    // ---- packed (broadcast) weights ----
    const ull w200d = pk2(__ldg(W2 + 0), __ldg(W2 + 0));
    const ull w201d = pk2(__ldg(W2 + 1), __ldg(W2 + 1));
    const ull w210d = pk2(__ldg(W2 + 2), __ldg(W2 + 2));
    const ull w211d = pk2(__ldg(W2 + 3), __ldg(W2 + 3));
    const ull B20d  = pk2(__ldg(b2 + 0), __ldg(b2 + 0));
    const ull B21d  = pk2(__ldg(b2 + 1), __ldg(b2 + 1));
    const ull w30d  = pk2(__ldg(W3 + 0), __ldg(W3 + 0));
    const ull w31d  = pk2(__ldg(W3 + 1), __ldg(W3 + 1));
    const ull B3d   = pk2(__ldg(b3 + 0), __ldg(b3 + 0));
    const ull k02d  = pk2(NEG_SLOPE, NEG_SLOPE);

    // ---- row features (3x LDG.128) ----
    const float4* fv = reinterpret_cast<const float4*>(F) + (size_t)t * 3;
    const float4 f0 = fv[0], f1 = fv[1], f2 = fv[2];
    const float xs[NV] = { f0.x, f0.y, f0.z, f0.w,
                           f1.x, f1.y, f1.z, f1.w,
                           f2.x, f2.y, f2.z, f2.w };

    // Layer-1 separable precompute over j (all 12 j's needed by both halves):
    //   p_h[j] = W1[h,0]*F[j] + b1[h];  a_h(i,j) = p_h[j] + W1[h,1]*F[i]
    ull P0[NV / 2], P1[NV / 2];
    #pragma unroll
    for (int jj = 0; jj < NV / 2; jj++) {
        P0[jj] = pk2(fmaf(w100, xs[2 * jj], B10), fmaf(w100, xs[2 * jj + 1], B10));
        P1[jj] = pk2(fmaf(w110, xs[2 * jj], B11), fmaf(w110, xs[2 * jj + 1], B11));
    }

    const int b = t >> 14;
    const int n = t & (SEQ_N - 1);
    float* outp = y + ((size_t)b * NV << 14) + n;

    float s1 = 0.f, s2 = 0.f;

    #pragma unroll
    for (int ii = 0; ii < NV / 2; ii++) {
        const int i = i0 + ii;
        const float xi = xs[i];
        const float q0 = w101 * xi;
        const float q1 = w111 * xi;
        const ull q0d = pk2(q0, q0);
        const ull q1d = pk2(q1, q1);
        ull acc = 0ull;                              // packed {0,0}
        #pragma unroll
        for (int jj = 0; jj < NV / 2; jj++) {
            ull a0 = add2(P0[jj], q0d);
            ull a1 = add2(P1[jj], q1d);
            a0 = leaky2(a0, k02d);
            a1 = leaky2(a1, k02d);
            ull g0 = fma2(w200d, a0, fma2(w201d, a1, B20d));
            ull g1 = fma2(w210d, a0, fma2(w211d, a1, B21d));
            g0 = leaky2(g0, k02d);
            g1 = leaky2(g1, k02d);
            ull o = fma2(w30d, g0, fma2(w31d, g1, B3d));
            o = leaky2(o, k02d);
            acc = add2(acc, o);
        }
        float m0, m1; upk2(acc, m0, m1);
        const float Ms = m0 + m1;                    // Msum[b,n,i]
        const float yv = fmaf(cw0, xi, fmaf(cw1, Ms, cb0));
        outp[(size_t)i << 14] = yv;                  // coalesced (consecutive n in warp)
        s1 += yv;
        s2 = fmaf(yv, yv, s2);
    }

    // ---- deterministic per-block (sum, sumsq) in double ----
    double d1 = (double)s1, d2 = (double)s2;
    #pragma unroll
    for (int o = 16; o > 0; o >>= 1) {
        d1 += __shfl_down_sync(0xffffffffu, d1, o);
        d2 += __shfl_down_sync(0xffffffffu, d2, o);
    }
    __shared__ double sh1[TPB_A / 32], sh2[TPB_A / 32];
    const int lane = tid & 31, warp = tid >> 5;
    if (lane == 0) { sh1[warp] = d1; sh2[warp] = d2; }
    __syncthreads();
    if (tid == 0) {
        double t1 = 0.0, t2 = 0.0;
        #pragma unroll
        for (int w = 0; w < TPB_A / 32; w++) { t1 += sh1[w]; t2 += sh2[w]; }
        g_partials[blockIdx.x] = make_double2(t1, t2);
    }
}

// ---------------------------------------------------------------------------
// Kernel C: each block redundantly reduces the 2048 partials (fixed-order,
// deterministic tree), derives the BN affine coefs, then normalizes its slice.
// ---------------------------------------------------------------------------
__global__ __launch_bounds__(TPB_C)
void nlmp_norm_kernel(const float* __restrict__ gamma, const float* __restrict__ beta,
                      float* __restrict__ y)
{
    const int tid = threadIdx.x;

    // Stats phase: 2048 partials, 16 per thread, fixed order.
    double a = 0.0, c = 0.0;
    const int base = tid * (NBLK_A / TPB_C);        // 16 each
    #pragma unroll
    for (int k = 0; k < NBLK_A / TPB_C; k++) {
        double2 v = g_partials[base + k];
        a += v.x; c += v.y;
    }
    __shared__ double r1[TPB_C], r2[TPB_C];
    r1[tid] = a; r2[tid] = c;
    __syncthreads();
    #pragma unroll
    for (int s = TPB_C / 2; s > 0; s >>= 1) {
        if (tid < s) { r1[tid] += r1[tid + s]; r2[tid] += r2[tid + s]; }
        __syncthreads();
    }
    __shared__ float2 s_coef;
    if (tid == 0) {
        const double M    = (double)TOTAL;
        const double mean = r1[0] / M;
        const double var  = r2[0] / M - mean * mean;   // biased
        const double rs   = 1.0 / sqrt(var + BN_EPS);
        const double gm   = (double)__ldg(gamma);
        s_coef = make_float2((float)(gm * rs),
                             (float)((double)__ldg(beta) - mean * gm * rs));
    }
    __syncthreads();
    const float sc = s_coef.x, sf = s_coef.y;

    // Normalize phase: 3 float4 per thread, coalesced.
    float4* p = reinterpret_cast<float4*>(y);
    const int blk = blockIdx.x * (TPB_C * 3);
    #pragma unroll
    for (int k = 0; k < 3; k++) {
        const int idx = blk + k * TPB_C + tid;
        float4 v = p[idx];
        v.x = leaky1(fmaf(v.x, sc, sf));
        v.y = leaky1(fmaf(v.y, sc, sf));
        v.z = leaky1(fmaf(v.z, sc, sf));
        v.w = leaky1(fmaf(v.w, sc, sf));
        p[idx] = v;
    }
}

// ---------------------------------------------------------------------------
extern "C" void kernel_launch(void* const* d_in, const int* in_sizes, int n_in,
                              void* d_out, int out_size)
{
    const float* F    = (const float*)d_in[0];
    const float* W1   = (const float*)d_in[1];
    const float* b1   = (const float*)d_in[2];
    const float* W2   = (const float*)d_in[3];
    const float* b2   = (const float*)d_in[4];
    const float* W3   = (const float*)d_in[5];
    const float* b3   = (const float*)d_in[6];
    const float* cw   = (const float*)d_in[7];
    const float* cb   = (const float*)d_in[8];
    const float* gmma = (const float*)d_in[9];
    const float* beta = (const float*)d_in[10];
    float* out = (float*)d_out;

    nlmp_main_kernel<<<NBLK_A, TPB_A>>>(F, W1, b1, W2, b2, W3, b3, cw, cb, out);
    nlmp_norm_kernel<<<NBLK_C, TPB_C>>>(gmma, beta, out);
}

// round 6
// speedup vs baseline: 1.2897x; 1.2897x over previous
#include <cuda_runtime.h>

// F[8,16384,12] f32 -> out [8,12,16384] f32
#define NV      12
#define SEQ_N   16384
#define ROWS    131072                  // 8 * 16384
#define TOTAL   (ROWS * NV)             // 1572864
#define TPB_A   128
#define ROWS_PER_BLK (TPB_A / 2)        // 64: two threads per row
#define NBLK_A  (ROWS / ROWS_PER_BLK)   // 2048
#define TPB_C   256
#define NBLK_C  ((TOTAL / 4) / TPB_C)   // 1536
#define NEG_SLOPE 0.2f
#define BN_EPS  1e-5

typedef unsigned long long ull;

// Scratch: device globals only. Zero-initialized at module load.
__device__ double2  g_partials[NBLK_A];
__device__ float2   g_coef;
__device__ unsigned g_arrive;           // self-resetting each launch

// ---------------- packed f32x2 helpers (sm_103a FFMA2 path) ----------------
__device__ __forceinline__ ull pk2(float a, float b) {
    ull r; asm("mov.b64 %0, {%1,%2};" : "=l"(r) : "f"(a), "f"(b)); return r;
}
__device__ __forceinline__ void upk2(ull v, float& a, float& b) {
    asm("mov.b64 {%0,%1}, %2;" : "=f"(a), "=f"(b) : "l"(v));
}
__device__ __forceinline__ ull add2(ull a, ull b) {
    ull r; asm("add.rn.f32x2 %0, %1, %2;" : "=l"(r) : "l"(a), "l"(b)); return r;
}
__device__ __forceinline__ ull mul2(ull a, ull b) {
    ull r; asm("mul.rn.f32x2 %0, %1, %2;" : "=l"(r) : "l"(a), "l"(b)); return r;
}
__device__ __forceinline__ ull fma2(ull a, ull b, ull c) {
    ull r; asm("fma.rn.f32x2 %0, %1, %2, %3;" : "=l"(r) : "l"(a), "l"(b), "l"(c)); return r;
}
// leaky per lane: max(x, 0.2x) = 1 packed FMUL2 + 2 scalar FMNMX (alu pipe).
__device__ __forceinline__ ull leaky2(ull v, ull k02) {
    ull t = mul2(v, k02);
    float v0, v1, t0, t1;
    upk2(v, v0, v1); upk2(t, t0, t1);
    return pk2(fmaxf(v0, t0), fmaxf(v1, t1));
}
__device__ __forceinline__ float leaky1(float x) { return fmaxf(x, NEG_SLOPE * x); }

// ---------------------------------------------------------------------------
// Kernel A: pair-MLP + conv, two threads per row. The LAST-arriving block also
// reduces the 2048 partials (fixed order -> deterministic) and publishes the
// BN affine coefs; no other block waits.
// ---------------------------------------------------------------------------
__global__ __launch_bounds__(TPB_A)
void nlmp_main_kernel(const float* __restrict__ F,
                      const float* __restrict__ W1, const float* __restrict__ b1,
                      const float* __restrict__ W2, const float* __restrict__ b2,
                      const float* __restrict__ W3, const float* __restrict__ b3,
                      const float* __restrict__ cw, const float* __restrict__ cb,
                      const float* __restrict__ gamma, const float* __restrict__ beta,
                      float* __restrict__ y)
{
    const int tid  = threadIdx.x;
    const int half = tid >> 6;                       // 0 or 1
    const int r    = tid & 63;                       // local row
    const int t    = blockIdx.x * ROWS_PER_BLK + r;  // global row id
    const int i0   = half * (NV / 2);                // first i of my half

    // ---- scalar weights ----
    const float w100 = __ldg(W1 + 0), w101 = __ldg(W1 + 1);
    const float w110 = __ldg(W1 + 2), w111 = __ldg(W1 + 3);
    const float B10  = __ldg(b1 + 0), B11  = __ldg(b1 + 1);
    const float cw0  = __ldg(cw + 0), cw1  = __ldg(cw + 1);
    const float cb0  = __ldg(cb + 0);

    // ---- packed (broadcast) weights ----
    const ull w200d = pk2(__ldg(W2 + 0), __ldg(W2 + 0));
    const ull w201d = pk2(__ldg(W2 + 1), __ldg(W2 + 1));
    const ull w210d = pk2(__ldg(W2 + 2), __ldg(W2 + 2));
    const ull w211d = pk2(__ldg(W2 + 3), __ldg(W2 + 3));
    const ull B20d  = pk2(__ldg(b2 + 0), __ldg(b2 + 0));
    const ull B21d  = pk2(__ldg(b2 + 1), __ldg(b2 + 1));
    const ull w30d  = pk2(__ldg(W3 + 0), __ldg(W3 + 0));
    const ull w31d  = pk2(__ldg(W3 + 1), __ldg(W3 + 1));
    const ull B3d   = pk2(__ldg(b3 + 0), __ldg(b3 + 0));
    const ull k02d  = pk2(NEG_SLOPE, NEG_SLOPE);

    // ---- row features (3x LDG.128) ----
    const float4* fv = reinterpret_cast<const float4*>(F) + (size_t)t * 3;
    const float4 f0 = fv[0], f1 = fv[1], f2 = fv[2];
    const float xs[NV] = { f0.x, f0.y, f0.z, f0.w,
                           f1.x, f1.y, f1.z, f1.w,
                           f2.x, f2.y, f2.z, f2.w };

    // Layer-1 separable precompute over all 12 j's:
    //   p_h[j] = W1[h,0]*F[j] + b1[h];  a_h(i,j) = p_h[j] + W1[h,1]*F[i]
    ull P0[NV / 2], P1[NV / 2];
    #pragma unroll
    for (int jj = 0; jj < NV / 2; jj++) {
        P0[jj] = pk2(fmaf(w100, xs[2 * jj], B10), fmaf(w100, xs[2 * jj + 1], B10));
        P1[jj] = pk2(fmaf(w110, xs[2 * jj], B11), fmaf(w110, xs[2 * jj + 1], B11));
    }

    const int b = t >> 14;
    const int n = t & (SEQ_N - 1);
    float* outp = y + ((size_t)b * NV << 14) + n;

    float s1 = 0.f, s2 = 0.f;

    #pragma unroll
    for (int ii = 0; ii < NV / 2; ii++) {
        const int i = i0 + ii;
        const float xi = xs[i];
        const float q0 = w101 * xi;
        const float q1 = w111 * xi;
        const ull q0d = pk2(q0, q0);
        const ull q1d = pk2(q1, q1);
        ull acc = 0ull;
        #pragma unroll
        for (int jj = 0; jj < NV / 2; jj++) {
            ull a0 = add2(P0[jj], q0d);
            ull a1 = add2(P1[jj], q1d);
            a0 = leaky2(a0, k02d);
            a1 = leaky2(a1, k02d);
            ull g0 = fma2(w200d, a0, fma2(w201d, a1, B20d));
            ull g1 = fma2(w210d, a0, fma2(w211d, a1, B21d));
            g0 = leaky2(g0, k02d);
            g1 = leaky2(g1, k02d);
            ull o = fma2(w30d, g0, fma2(w31d, g1, B3d));
            o = leaky2(o, k02d);
            acc = add2(acc, o);
        }
        float m0, m1; upk2(acc, m0, m1);
        const float Ms = m0 + m1;                    // Msum[b,n,i]
        const float yv = fmaf(cw0, xi, fmaf(cw1, Ms, cb0));
        outp[(size_t)i << 14] = yv;                  // coalesced
        s1 += yv;
        s2 = fmaf(yv, yv, s2);
    }

    // ---- deterministic per-block (sum, sumsq) in double ----
    double d1 = (double)s1, d2 = (double)s2;
    #pragma unroll
    for (int o = 16; o > 0; o >>= 1) {
        d1 += __shfl_down_sync(0xffffffffu, d1, o);
        d2 += __shfl_down_sync(0xffffffffu, d2, o);
    }
    __shared__ double sh1[TPB_A / 32], sh2[TPB_A / 32];
    const int lane = tid & 31, warp = tid >> 5;
    if (lane == 0) { sh1[warp] = d1; sh2[warp] = d2; }
    __syncthreads();

    __shared__ bool s_last;
    if (tid == 0) {
        double t1 = 0.0, t2 = 0.0;
        #pragma unroll
        for (int w = 0; w < TPB_A / 32; w++) { t1 += sh1[w]; t2 += sh2[w]; }
        g_partials[blockIdx.x] = make_double2(t1, t2);
        __threadfence();
        s_last = (atomicAdd(&g_arrive, 1u) == NBLK_A - 1u);
    }
    __syncthreads();

    // Last-arriving block reduces all partials (fixed order) and publishes coefs.
    if (s_last) {
        __threadfence();                              // acquire all partials
        double a = 0.0, c = 0.0;
        const int base = tid * (NBLK_A / TPB_A);      // 16 each
        #pragma unroll
        for (int k = 0; k < NBLK_A / TPB_A; k++) {
            double2 v = g_partials[base + k];
            a += v.x; c += v.y;
        }
        __shared__ double r1[TPB_A], r2[TPB_A];
        r1[tid] = a; r2[tid] = c;
        __syncthreads();
        #pragma unroll
        for (int s = TPB_A / 2; s > 0; s >>= 1) {
            if (tid < s) { r1[tid] += r1[tid + s]; r2[tid] += r2[tid + s]; }
            __syncthreads();
        }
        if (tid == 0) {
            const double M    = (double)TOTAL;
            const double mean = r1[0] / M;
            const double var  = r2[0] / M - mean * mean;   // biased
            const double rs   = 1.0 / sqrt(var + BN_EPS);
            const double gm   = (double)__ldg(gamma);
            g_coef = make_float2((float)(gm * rs),
                                 (float)((double)__ldg(beta) - mean * gm * rs));
            g_arrive = 0u;                            // reset for next replay
        }
    }
}

// ---------------------------------------------------------------------------
// Kernel C: trivial normalize + leaky. One float4 per thread, coalesced.
// g_coef visibility is guaranteed by the kernel-boundary dependency.
// ---------------------------------------------------------------------------
__global__ __launch_bounds__(TPB_C)
void nlmp_norm_kernel(float* __restrict__ y)
{
    const float2 c = g_coef;
    const int idx = blockIdx.x * TPB_C + threadIdx.x;
    float4* p = reinterpret_cast<float4*>(y);
    float4 v = p[idx];
    v.x = leaky1(fmaf(v.x, c.x, c.y));
    v.y = leaky1(fmaf(v.y, c.x, c.y));
    v.z = leaky1(fmaf(v.z, c.x, c.y));
    v.w = leaky1(fmaf(v.w, c.x, c.y));
    p[idx] = v;
}

// ---------------------------------------------------------------------------
extern "C" void kernel_launch(void* const* d_in, const int* in_sizes, int n_in,
                              void* d_out, int out_size)
{
    const float* F    = (const float*)d_in[0];
    const float* W1   = (const float*)d_in[1];
    const float* b1   = (const float*)d_in[2];
    const float* W2   = (const float*)d_in[3];
    const float* b2   = (const float*)d_in[4];
    const float* W3   = (const float*)d_in[5];
    const float* b3   = (const float*)d_in[6];
    const float* cw   = (const float*)d_in[7];
    const float* cb   = (const float*)d_in[8];
    const float* gmma = (const float*)d_in[9];
    const float* beta = (const float*)d_in[10];
    float* out = (float*)d_out;

    nlmp_main_kernel<<<NBLK_A, TPB_A>>>(F, W1, b1, W2, b2, W3, b3, cw, cb,
                                        gmma, beta, out);
    nlmp_norm_kernel<<<NBLK_C, TPB_C>>>(out);
}

// round 7
// speedup vs baseline: 1.4100x; 1.0932x over previous
#include <cuda_runtime.h>

// F[8,16384,12] f32 -> out [8,12,16384] f32
#define NV      12
#define SEQ_N   16384
#define ROWS    131072                  // 8 * 16384
#define TOTAL   (ROWS * NV)             // 1572864
#define TPB_A   128
#define ROWS_PER_BLK (TPB_A / 2)        // 64: two threads per row
#define NBLK_A  (ROWS / ROWS_PER_BLK)   // 2048
#define TPB_C   512
#define VEC_C   2                       // independent float4 per thread (MLP)
#define NBLK_C  ((TOTAL / 4) / (TPB_C * VEC_C))   // 384
#define NEG_SLOPE 0.2f
#define BN_EPS  1e-5

typedef unsigned long long ull;

// Scratch: device globals only. Zero-initialized at module load.
__device__ double2  g_partials[NBLK_A];
__device__ float2   g_coef;
__device__ unsigned g_arrive;           // self-resetting each launch

// ---------------- packed f32x2 helpers (sm_103a FFMA2 path) ----------------
__device__ __forceinline__ ull pk2(float a, float b) {
    ull r; asm("mov.b64 %0, {%1,%2};" : "=l"(r) : "f"(a), "f"(b)); return r;
}
__device__ __forceinline__ void upk2(ull v, float& a, float& b) {
    asm("mov.b64 {%0,%1}, %2;" : "=f"(a), "=f"(b) : "l"(v));
}
__device__ __forceinline__ ull add2(ull a, ull b) {
    ull r; asm("add.rn.f32x2 %0, %1, %2;" : "=l"(r) : "l"(a), "l"(b)); return r;
}
__device__ __forceinline__ ull mul2(ull a, ull b) {
    ull r; asm("mul.rn.f32x2 %0, %1, %2;" : "=l"(r) : "l"(a), "l"(b)); return r;
}
__device__ __forceinline__ ull fma2(ull a, ull b, ull c) {
    ull r; asm("fma.rn.f32x2 %0, %1, %2, %3;" : "=l"(r) : "l"(a), "l"(b), "l"(c)); return r;
}
// leaky per lane: max(x, 0.2x) = 1 packed FMUL2 + 2 scalar FMNMX (alu pipe).
__device__ __forceinline__ ull leaky2(ull v, ull k02) {
    ull t = mul2(v, k02);
    float v0, v1, t0, t1;
    upk2(v, v0, v1); upk2(t, t0, t1);
    return pk2(fmaxf(v0, t0), fmaxf(v1, t1));
}
__device__ __forceinline__ float leaky1(float x) { return fmaxf(x, NEG_SLOPE * x); }

// ---------------------------------------------------------------------------
// Kernel A: pair-MLP + conv, two threads per row. The LAST-arriving block also
// reduces the 2048 partials (fixed order -> deterministic) and publishes the
// BN affine coefs; no other block waits.
// ---------------------------------------------------------------------------
__global__ __launch_bounds__(TPB_A)
void nlmp_main_kernel(const float* __restrict__ F,
                      const float* __restrict__ W1, const float* __restrict__ b1,
                      const float* __restrict__ W2, const float* __restrict__ b2,
                      const float* __restrict__ W3, const float* __restrict__ b3,
                      const float* __restrict__ cw, const float* __restrict__ cb,
                      const float* __restrict__ gamma, const float* __restrict__ beta,
                      float* __restrict__ y)
{
    const int tid  = threadIdx.x;
    const int half = tid >> 6;                       // 0 or 1
    const int r    = tid & 63;                       // local row
    const int t    = blockIdx.x * ROWS_PER_BLK + r;  // global row id
    const int i0   = half * (NV / 2);                // first i of my half

    // ---- scalar weights ----
    const float w100 = __ldg(W1 + 0), w101 = __ldg(W1 + 1);
    const float w110 = __ldg(W1 + 2), w111 = __ldg(W1 + 3);
    const float B10  = __ldg(b1 + 0), B11  = __ldg(b1 + 1);
    const float cw0  = __ldg(cw + 0), cw1  = __ldg(cw + 1);
    const float cb0  = __ldg(cb + 0);

    // ---- packed (broadcast) weights ----
    const ull w200d = pk2(__ldg(W2 + 0), __ldg(W2 + 0));
    const ull w201d = pk2(__ldg(W2 + 1), __ldg(W2 + 1));
    const ull w210d = pk2(__ldg(W2 + 2), __ldg(W2 + 2));
    const ull w211d = pk2(__ldg(W2 + 3), __ldg(W2 + 3));
    const ull B20d  = pk2(__ldg(b2 + 0), __ldg(b2 + 0));
    const ull B21d  = pk2(__ldg(b2 + 1), __ldg(b2 + 1));
    const ull w30d  = pk2(__ldg(W3 + 0), __ldg(W3 + 0));
    const ull w31d  = pk2(__ldg(W3 + 1), __ldg(W3 + 1));
    const ull B3d   = pk2(__ldg(b3 + 0), __ldg(b3 + 0));
    const ull k02d  = pk2(NEG_SLOPE, NEG_SLOPE);

    // ---- row features (3x LDG.128) ----
    const float4* fv = reinterpret_cast<const float4*>(F) + (size_t)t * 3;
    const float4 f0 = fv[0], f1 = fv[1], f2 = fv[2];
    const float xs[NV] = { f0.x, f0.y, f0.z, f0.w,
                           f1.x, f1.y, f1.z, f1.w,
                           f2.x, f2.y, f2.z, f2.w };

    // Layer-1 separable precompute over all 12 j's:
    //   p_h[j] = W1[h,0]*F[j] + b1[h];  a_h(i,j) = p_h[j] + W1[h,1]*F[i]
    ull P0[NV / 2], P1[NV / 2];
    #pragma unroll
    for (int jj = 0; jj < NV / 2; jj++) {
        P0[jj] = pk2(fmaf(w100, xs[2 * jj], B10), fmaf(w100, xs[2 * jj + 1], B10));
        P1[jj] = pk2(fmaf(w110, xs[2 * jj], B11), fmaf(w110, xs[2 * jj + 1], B11));
    }

    const int b = t >> 14;
    const int n = t & (SEQ_N - 1);
    float* outp = y + ((size_t)b * NV << 14) + n;

    float s1 = 0.f, s2 = 0.f;

    #pragma unroll
    for (int ii = 0; ii < NV / 2; ii++) {
        const int i = i0 + ii;
        const float xi = xs[i];
        const float q0 = w101 * xi;
        const float q1 = w111 * xi;
        const ull q0d = pk2(q0, q0);
        const ull q1d = pk2(q1, q1);
        ull acc = 0ull;
        #pragma unroll
        for (int jj = 0; jj < NV / 2; jj++) {
            ull a0 = add2(P0[jj], q0d);
            ull a1 = add2(P1[jj], q1d);
            a0 = leaky2(a0, k02d);
            a1 = leaky2(a1, k02d);
            ull g0 = fma2(w200d, a0, fma2(w201d, a1, B20d));
            ull g1 = fma2(w210d, a0, fma2(w211d, a1, B21d));
            g0 = leaky2(g0, k02d);
            g1 = leaky2(g1, k02d);
            ull o = fma2(w30d, g0, fma2(w31d, g1, B3d));
            o = leaky2(o, k02d);
            acc = add2(acc, o);
        }
        float m0, m1; upk2(acc, m0, m1);
        const float Ms = m0 + m1;                    // Msum[b,n,i]
        const float yv = fmaf(cw0, xi, fmaf(cw1, Ms, cb0));
        outp[(size_t)i << 14] = yv;                  // coalesced
        s1 += yv;
        s2 = fmaf(yv, yv, s2);
    }

    // ---- deterministic per-block (sum, sumsq) in double ----
    double d1 = (double)s1, d2 = (double)s2;
    #pragma unroll
    for (int o = 16; o > 0; o >>= 1) {
        d1 += __shfl_down_sync(0xffffffffu, d1, o);
        d2 += __shfl_down_sync(0xffffffffu, d2, o);
    }
    __shared__ double sh1[TPB_A / 32], sh2[TPB_A / 32];
    const int lane = tid & 31, warp = tid >> 5;
    if (lane == 0) { sh1[warp] = d1; sh2[warp] = d2; }
    __syncthreads();

    __shared__ bool s_last;
    if (tid == 0) {
        double t1 = 0.0, t2 = 0.0;
        #pragma unroll
        for (int w = 0; w < TPB_A / 32; w++) { t1 += sh1[w]; t2 += sh2[w]; }
        g_partials[blockIdx.x] = make_double2(t1, t2);
        __threadfence();
        s_last = (atomicAdd(&g_arrive, 1u) == NBLK_A - 1u);
    }
    __syncthreads();

    // Last-arriving block reduces all partials (fixed order) and publishes coefs.
    if (s_last) {
        __threadfence();                              // acquire all partials
        double a = 0.0, c = 0.0;
        const int base = tid * (NBLK_A / TPB_A);      // 16 each, independent loads
        #pragma unroll
        for (int k = 0; k < NBLK_A / TPB_A; k++) {
            double2 v = g_partials[base + k];
            a += v.x; c += v.y;
        }
        // warp reduce, then cross-warp via shared (single sync)
        #pragma unroll
        for (int o = 16; o > 0; o >>= 1) {
            a += __shfl_down_sync(0xffffffffu, a, o);
            c += __shfl_down_sync(0xffffffffu, c, o);
        }
        __shared__ double w1s[TPB_A / 32], w2s[TPB_A / 32];
        if (lane == 0) { w1s[warp] = a; w2s[warp] = c; }
        __syncthreads();
        if (tid == 0) {
            double t1 = 0.0, t2 = 0.0;
            #pragma unroll
            for (int w = 0; w < TPB_A / 32; w++) { t1 += w1s[w]; t2 += w2s[w]; }
            const double M    = (double)TOTAL;
            const double mean = t1 / M;
            const double var  = t2 / M - mean * mean;   // biased
            const double rs   = 1.0 / sqrt(var + BN_EPS);
            const double gm   = (double)__ldg(gamma);
            g_coef = make_float2((float)(gm * rs),
                                 (float)((double)__ldg(beta) - mean * gm * rs));
            g_arrive = 0u;                            // reset for next replay
        }
    }
}

// ---------------------------------------------------------------------------
// Kernel C: normalize + leaky. VEC_C independent float4 per thread (MLP),
// 384 blocks -> single wave, throughput-bound on L2.
// ---------------------------------------------------------------------------
__global__ __launch_bounds__(TPB_C)
void nlmp_norm_kernel(float* __restrict__ y)
{
    const float2 c = g_coef;
    float4* p = reinterpret_cast<float4*>(y);
    const int base = blockIdx.x * (TPB_C * VEC_C) + threadIdx.x;

    float4 v[VEC_C];
    #pragma unroll
    for (int k = 0; k < VEC_C; k++)                   // independent loads first
        v[k] = p[base + k * TPB_C];
    #pragma unroll
    for (int k = 0; k < VEC_C; k++) {
        v[k].x = leaky1(fmaf(v[k].x, c.x, c.y));
        v[k].y = leaky1(fmaf(v[k].y, c.x, c.y));
        v[k].z = leaky1(fmaf(v[k].z, c.x, c.y));
        v[k].w = leaky1(fmaf(v[k].w, c.x, c.y));
        p[base + k * TPB_C] = v[k];
    }
}

// ---------------------------------------------------------------------------
extern "C" void kernel_launch(void* const* d_in, const int* in_sizes, int n_in,
                              void* d_out, int out_size)
{
    const float* F    = (const float*)d_in[0];
    const float* W1   = (const float*)d_in[1];
    const float* b1   = (const float*)d_in[2];
    const float* W2   = (const float*)d_in[3];
    const float* b2   = (const float*)d_in[4];
    const float* W3   = (const float*)d_in[5];
    const float* b3   = (const float*)d_in[6];
    const float* cw   = (const float*)d_in[7];
    const float* cb   = (const float*)d_in[8];
    const float* gmma = (const float*)d_in[9];
    const float* beta = (const float*)d_in[10];
    float* out = (float*)d_out;

    nlmp_main_kernel<<<NBLK_A, TPB_A>>>(F, W1, b1, W2, b2, W3, b3, cw, cb,
                                        gmma, beta, out);
    nlmp_norm_kernel<<<NBLK_C, TPB_C>>>(out);
}